// round 15
// baseline (speedup 1.0000x reference)
#include <cuda_runtime.h>
#include <cuda_bf16.h>
#include <cstdint>

// GAT fused kernel, GB300 sm_103a.
// B=8, N=512, T=128, DIN=DOUT=128, H=8, HD=16.
//
// Factorization (exactly equivalent to reference):
//   softmax-effective score[b,t,h,n] = h[b,n,t,:] . wtil_h   (row-constant terms cancel)
//     wtil_h[k] = sum_d W1[k, h*16+d] * Wa[16+d]
//   e = mask * exp(score);  w = e * rv,  rv = 1/(adj==0 ? 1e9 : adj)
//   Z_h = sum_n e;  S_h = (sum_n w)/Z_h;  g_h = (sum_n w*h_n)/Z_h
//   agg[h*16+d] = g_h . W1[:, h*16+d] + S_h * b1[h*16+d]
//   th = h0 @ W1 + b1
//   out = agg @ W2[:128] + th @ W2[128:] + b2
//
// R15: cp.async 3-deep 64-row ring (in-flight DMA ~68KB/block; the kernel was
// MLP-bound at a constant 1.7TB/s across R8-R14) + the register compute of
// R14: per row-pair, score partials from the same registers as the G update,
// 9-ull ownership-halving butterfly, shfl-gather of w, f32x2 G accumulators.

#define Bv 8
#define Nv 512
#define Tv 128
#define Dv 128
#define CH 64
#define NCHUNK 8
#define ROWP 132   // padded row pitch (floats); col 128 carries enc

typedef unsigned long long ull;

// ---------------- scratch ----------------
__device__ float G_scr[Bv * Tv * 8 * Dv];
__device__ float S_scr[Bv * Tv * 8];

// ---------------- f32x2 helpers ----------------
__device__ __forceinline__ ull f2fma(ull a, ull b, ull c) {
    ull d; asm("fma.rn.f32x2 %0,%1,%2,%3;" : "=l"(d) : "l"(a), "l"(b), "l"(c)); return d;
}
__device__ __forceinline__ ull f2add(ull a, ull b) {
    ull d; asm("add.rn.f32x2 %0,%1,%2;" : "=l"(d) : "l"(a), "l"(b)); return d;
}
__device__ __forceinline__ ull f2mul(ull a, ull b) {
    ull d; asm("mul.rn.f32x2 %0,%1,%2;" : "=l"(d) : "l"(a), "l"(b)); return d;
}
__device__ __forceinline__ ull packrep(float x) {
    ull d; asm("mov.b64 %0,{%1,%1};" : "=l"(d) : "f"(x)); return d;
}
__device__ __forceinline__ ull pack2(float x, float y) {
    ull d; asm("mov.b64 %0,{%1,%2};" : "=l"(d) : "f"(x), "f"(y)); return d;
}
__device__ __forceinline__ float2 unpk(ull a) {
    float2 r; asm("mov.b64 {%0,%1},%2;" : "=f"(r.x), "=f"(r.y) : "l"(a)); return r;
}

// ---------------- main ----------------
// dynamic smem layout (floats):
//   hbuf : 3 * CH * ROWP = 25344  @ 0       (ring of 64-row chunks)
//   wts  : 8 * ROWP      = 1056   @ 25344
//   zred : 64                     @ 26400
//   wred : 64                     @ 26464
//   invZ : 8                      @ 26528
//   was  : 16                     @ 26536
#define MAIN_SMEM_FLOATS 26552

__global__ __launch_bounds__(256, 2) void gat_main(const float* __restrict__ hin,
                                                   const float* __restrict__ adj,
                                                   const float* __restrict__ mask,
                                                   const float* __restrict__ W1,
                                                   const float* __restrict__ Wa) {
    extern __shared__ __align__(16) float sm[];
    float* hbuf = sm;
    float* wts  = sm + 25344;
    float* zred = sm + 26400;
    float* wred = sm + 26464;
    float* invZ = sm + 26528;
    float* was  = sm + 26536;

    const int bt = blockIdx.x;
    const int b = bt >> 7;
    const int t = bt & 127;
    const int tid = threadIdx.x;
    const int warp = tid >> 5;
    const int lane = tid & 31;
    const int kc = lane;

    float enc0, enc1;   // signed 1/adj for rows tid, tid+256

    // ---- pure-DMA chunk loader ----
    auto issue_dma = [&](int c) {
        float* hb = hbuf + (c % 3) * (CH * ROWP);
        const float* base = hin + (((size_t)(b * Nv + c * CH)) * Tv + t) * Dv;
        #pragma unroll
        for (int i = 0; i < 8; i++) {
            int lin = i * 256 + tid;
            int r = lin >> 5;
            int j = lin & 31;
            const float* gp = base + (size_t)r * (Tv * Dv) + j * 4;
            unsigned sa = (unsigned)__cvta_generic_to_shared(&hb[r * ROWP + j * 4]);
            asm volatile("cp.async.cg.shared.global [%0], [%1], 16;" :: "r"(sa), "l"(gp));
        }
        asm volatile("cp.async.commit_group;");
    };
    // ---- enc pad store for chunk c (plain STS, fenced by __syncthreads) ----
    auto pads = [&](int c) {
        float* hb = hbuf + (c % 3) * (CH * ROWP);
        if ((tid >> 6) == c)     hb[(tid & 63) * ROWP + 128] = enc0;
        if ((tid >> 6) == c - 4) hb[(tid & 63) * ROWP + 128] = enc1;
    };

    // DMA for first 3 chunks goes out immediately
    issue_dma(0); issue_dma(1); issue_dma(2);

    // enc compute overlaps the DMA
    {
        float m0 = mask[(size_t)(b * Nv + tid) * Tv + t];
        float m1 = mask[(size_t)(b * Nv + tid + 256) * Tv + t];
        float a0 = adj[(size_t)(b * Tv + t) * Nv + tid];
        float a1 = adj[(size_t)(b * Tv + t) * Nv + tid + 256];
        a0 = (a0 == 0.f) ? 1e9f : a0;
        a1 = (a1 == 0.f) ? 1e9f : a1;
        enc0 = (m0 > 0.5f ? 1.f : -1.f) * (1.0f / a0);
        enc1 = (m1 > 0.5f ? 1.f : -1.f) * (1.0f / a1);
    }
    pads(0); pads(1); pads(2);

    // wtil into smem (overlaps DMA)
    if (tid < 16) was[tid] = Wa[16 + tid];
    __syncthreads();
    for (int idx = tid; idx < 1024; idx += 256) {
        int hh = idx >> 7, k = idx & 127;
        const float* w1p = W1 + k * 128 + hh * 16;
        float a = 0.f;
        #pragma unroll
        for (int d = 0; d < 16; d++)
            a = fmaf(w1p[d], was[d], a);
        wts[hh * ROWP + k] = a;
    }
    __syncthreads();

    // wtil column-slice in registers
    ull wreg[16];
    #pragma unroll
    for (int h = 0; h < 8; h++) {
        ulonglong2 wv = *(const ulonglong2*)&wts[h * ROWP + kc * 4];
        wreg[2 * h] = wv.x;
        wreg[2 * h + 1] = wv.y;
    }

    ull acc[16];
    #pragma unroll
    for (int q = 0; q < 16; q++) acc[q] = 0ull;
    float zsum = 0.f, wsum = 0.f;

    const bool bb16 = (lane & 16) != 0;
    const bool bb8  = (lane & 8) != 0;
    const bool bb4  = (lane & 4) != 0;

    #pragma unroll 1
    for (int c = 0; c < NCHUNK; c++) {
        // graduated wait keeps 2 chunks of DMA in flight
        if (c < 6)       { asm volatile("cp.async.wait_group 2;"); }
        else if (c == 6) { asm volatile("cp.async.wait_group 1;"); }
        else             { asm volatile("cp.async.wait_group 0;"); }
        __syncthreads();
        const float* hb = hbuf + (c % 3) * (CH * ROWP);

        #pragma unroll
        for (int pr = 0; pr < 4; pr++) {
            const int r = warp * 8 + pr * 2;        // row within chunk
            ulonglong2 xa = *(const ulonglong2*)&hb[r * ROWP + kc * 4];
            ulonglong2 xb = *(const ulonglong2*)&hb[(r + 1) * ROWP + kc * 4];

            // score partials: sp[h] = (row r partial, row r+1 partial)
            ull sp[8];
            #pragma unroll
            for (int h = 0; h < 8; h++) {
                ull pa = f2fma(xa.y, wreg[2 * h + 1], f2mul(xa.x, wreg[2 * h]));
                ull pb = f2fma(xb.y, wreg[2 * h + 1], f2mul(xb.x, wreg[2 * h]));
                float2 qa = unpk(pa);
                float2 qb = unpk(pb);
                sp[h] = pack2(qa.x + qa.y, qb.x + qb.y);
            }

            // ownership-halving butterfly: quad q ends holding head q's scores
            ull v4[4];
            #pragma unroll
            for (int j = 0; j < 4; j++) {
                ull keep = bb16 ? sp[j + 4] : sp[j];
                ull send = bb16 ? sp[j] : sp[j + 4];
                v4[j] = f2add(keep, __shfl_xor_sync(0xffffffffu, send, 16));
            }
            ull v2[2];
            #pragma unroll
            for (int j = 0; j < 2; j++) {
                ull keep = bb8 ? v4[j + 2] : v4[j];
                ull send = bb8 ? v4[j] : v4[j + 2];
                v2[j] = f2add(keep, __shfl_xor_sync(0xffffffffu, send, 8));
            }
            ull v1;
            {
                ull keep = bb4 ? v2[1] : v2[0];
                ull send = bb4 ? v2[0] : v2[1];
                v1 = f2add(keep, __shfl_xor_sync(0xffffffffu, send, 4));
            }
            v1 = f2add(v1, __shfl_xor_sync(0xffffffffu, v1, 2));
            v1 = f2add(v1, __shfl_xor_sync(0xffffffffu, v1, 1));

            // e / w for owned head (all 4 lanes of quad hold identical v1)
            float en0 = hb[r * ROWP + 128];
            float en1 = hb[(r + 1) * ROWP + 128];
            float2 s = unpk(v1);
            float e0 = (en0 > 0.f) ? __expf(s.x) : 0.f;
            float e1 = (en1 > 0.f) ? __expf(s.y) : 0.f;
            float w0 = e0 * fabsf(en0);
            float w1 = e1 * fabsf(en1);
            zsum += e0 + e1;
            wsum += w0 + w1;

            // gather all heads' w via independent shuffles (quad h holds head h)
            ull wp = pack2(w0, w1);
            #pragma unroll
            for (int h = 0; h < 8; h++) {
                ull wh = __shfl_sync(0xffffffffu, wp, h * 4);
                float2 wf = unpk(wh);
                ull wr0 = packrep(wf.x);
                ull wr1 = packrep(wf.y);
                acc[2 * h]     = f2fma(wr0, xa.x, acc[2 * h]);
                acc[2 * h]     = f2fma(wr1, xb.x, acc[2 * h]);
                acc[2 * h + 1] = f2fma(wr0, xa.y, acc[2 * h + 1]);
                acc[2 * h + 1] = f2fma(wr1, xb.y, acc[2 * h + 1]);
            }
        }
        __syncthreads();                 // everyone done reading buf c%3
        if (c + 3 < NCHUNK) { issue_dma(c + 3); pads(c + 3); }
    }

    // ---- reduce Z, Sw per head (lane 4h of each warp holds head h) ----
    if ((lane & 3) == 0) {
        zred[warp * 8 + (lane >> 2)] = zsum;
        wred[warp * 8 + (lane >> 2)] = wsum;
    }
    __syncthreads();
    if (tid < 8) {
        float Z = 0.f, W = 0.f;
        #pragma unroll
        for (int i = 0; i < 8; i++) { Z += zred[i * 8 + tid]; W += wred[i * 8 + tid]; }
        float iZ = 1.0f / Z;
        invZ[tid] = iZ;
        S_scr[bt * 8 + tid] = W * iZ;
    }

    // ---- dump per-thread G partials into (reused) hbuf, tree-reduce, write ----
    {
        ull* red = (ull*)hbuf;   // 256 threads * 16 ull = 32 KB
        ulonglong2* my = (ulonglong2*)(red + (size_t)tid * 16);
        #pragma unroll
        for (int q = 0; q < 8; q++)
            my[q] = make_ulonglong2(acc[2 * q], acc[2 * q + 1]);
    }
    __syncthreads();
    {
        const ull* red = (const ull*)hbuf;
        #pragma unroll
        for (int o = 0; o < 2; o++) {
            int oi = tid * 2 + o;          // 0..511
            int hh  = oi >> 6;
            int kc2 = oi & 63;
            int kcc = kc2 >> 1, p = kc2 & 1;
            ull s = red[((size_t)kcc) * 16 + hh * 2 + p];
            #pragma unroll
            for (int g = 1; g < 8; g++)
                s = f2add(s, red[((size_t)(g * 32 + kcc)) * 16 + hh * 2 + p]);
            s = f2mul(s, packrep(invZ[hh]));
            ((ull*)G_scr)[(size_t)bt * 512 + hh * 64 + kc2] = s;
        }
    }
}

// ---------------- epilogue: 1024 lightweight blocks ----------------
__global__ __launch_bounds__(128) void gat_epi(const float* __restrict__ hin,
                                               const float* __restrict__ W1,
                                               const float* __restrict__ W2,
                                               const float* __restrict__ b1,
                                               const float* __restrict__ b2,
                                               float* __restrict__ out) {
    __shared__ __align__(16) float gs[8 * 132];
    __shared__ __align__(16) float h0s[128];
    __shared__ __align__(16) float aggs[128];
    __shared__ __align__(16) float ths[128];
    __shared__ float Ss[8];

    const int bt = blockIdx.x;
    const int b = bt >> 7;
    const int t = bt & 127;
    const int tid = threadIdx.x;

    #pragma unroll
    for (int i = 0; i < 8; i++) {
        int idx = i * 128 + tid;
        gs[(idx >> 7) * 132 + (idx & 127)] = G_scr[(size_t)bt * 1024 + idx];
    }
    h0s[tid] = hin[((size_t)(b * Nv) * Tv + t) * Dv + tid];
    if (tid < 8) Ss[tid] = S_scr[bt * 8 + tid];
    __syncthreads();

    {
        const int j = tid;
        const int hh = j >> 4;
        float bj = __ldg(&b1[j]);
        float agg = Ss[hh] * bj;
        float th = bj;
        const float* gp = &gs[hh * 132];
        #pragma unroll 8
        for (int m = 0; m < 128; m++) {
            float w = __ldg(&W1[m * 128 + j]);
            agg = fmaf(gp[m], w, agg);
            th  = fmaf(h0s[m], w, th);
        }
        aggs[j] = agg;
        ths[j] = th;
    }
    __syncthreads();

    {
        const int k = tid;
        float o = __ldg(&b2[k]);
        #pragma unroll 8
        for (int j = 0; j < 128; j++) {
            o = fmaf(aggs[j], __ldg(&W2[j * 128 + k]), o);
            o = fmaf(ths[j],  __ldg(&W2[(128 + j) * 128 + k]), o);
        }
        out[(size_t)bt * 128 + k] = o;
    }
}

// third kernel: keeps ncu's fixed capture slot on gat_main
__global__ void gat_nop() {}

// ---------------- launch ----------------
extern "C" void kernel_launch(void* const* d_in, const int* in_sizes, int n_in,
                              void* d_out, int out_size) {
    const float* h    = (const float*)d_in[0];
    const float* adj  = (const float*)d_in[1];
    const float* mask = (const float*)d_in[2];
    const float* W1   = (const float*)d_in[3];
    const float* b1   = (const float*)d_in[4];
    const float* Wa   = (const float*)d_in[5];
    // d_in[6] = ba (cancels in softmax; unused)
    const float* W2   = (const float*)d_in[7];
    const float* b2   = (const float*)d_in[8];
    float* out = (float*)d_out;

    cudaFuncSetAttribute(gat_main, cudaFuncAttributeMaxDynamicSharedMemorySize,
                         MAIN_SMEM_FLOATS * (int)sizeof(float));

    gat_main<<<Bv * Tv, 256, MAIN_SMEM_FLOATS * sizeof(float)>>>(h, adj, mask, W1, Wa);
    gat_epi<<<Bv * Tv, 128>>>(h, W1, W2, b1, b2, out);
    gat_nop<<<1, 32>>>();
}

// round 16
// speedup vs baseline: 1.0294x; 1.0294x over previous
#include <cuda_runtime.h>
#include <cuda_bf16.h>
#include <cstdint>

// GAT fused kernel, GB300 sm_103a.
// B=8, N=512, T=128, DIN=DOUT=128, H=8, HD=16.
//
// Factorization (exactly equivalent to reference):
//   softmax-effective score[b,t,h,n] = h[b,n,t,:] . wtil_h   (row-constant terms cancel)
//     wtil_h[k] = sum_d W1[k, h*16+d] * Wa[16+d]
//   e = mask * exp(score);  w = e * rv,  rv = 1/(adj==0 ? 1e9 : adj)
//   Z_h = sum_n e;  S_h = (sum_n w)/Z_h;  g_h = (sum_n w*h_n)/Z_h
//   agg[h*16+d] = g_h . W1[:, h*16+d] + S_h * b1[h*16+d]
//   th = h0 @ W1 + b1
//   out = agg @ W2[:128] + th @ W2[128:] + b2
//
// R16: R15's cp.async ring-3 staging + butterfly scores, with the w-gather
// shuffles (16 shfl.32 per row-pair) replaced by a per-warp smem broadcast
// (R14's trick). The kernel has been SHFL-throughput bound on the MIO/crossbar
// (L1 66-89% across R11-R15 with constant DRAM ~20%); this cuts per-row-pair
// shfl.32 from 34 to 18. enc (signed 1/adj) moved to a one-time smem table.

#define Bv 8
#define Nv 512
#define Tv 128
#define Dv 128
#define CH 64
#define NCHUNK 8
#define ROWP 132   // padded row pitch (floats)

typedef unsigned long long ull;

// ---------------- scratch ----------------
__device__ float G_scr[Bv * Tv * 8 * Dv];
__device__ float S_scr[Bv * Tv * 8];

// ---------------- f32x2 helpers ----------------
__device__ __forceinline__ ull f2fma(ull a, ull b, ull c) {
    ull d; asm("fma.rn.f32x2 %0,%1,%2,%3;" : "=l"(d) : "l"(a), "l"(b), "l"(c)); return d;
}
__device__ __forceinline__ ull f2add(ull a, ull b) {
    ull d; asm("add.rn.f32x2 %0,%1,%2;" : "=l"(d) : "l"(a), "l"(b)); return d;
}
__device__ __forceinline__ ull f2mul(ull a, ull b) {
    ull d; asm("mul.rn.f32x2 %0,%1,%2;" : "=l"(d) : "l"(a), "l"(b)); return d;
}
__device__ __forceinline__ ull packrep(float x) {
    ull d; asm("mov.b64 %0,{%1,%1};" : "=l"(d) : "f"(x)); return d;
}
__device__ __forceinline__ ull pack2(float x, float y) {
    ull d; asm("mov.b64 %0,{%1,%2};" : "=l"(d) : "f"(x), "f"(y)); return d;
}
__device__ __forceinline__ float2 unpk(ull a) {
    float2 r; asm("mov.b64 {%0,%1},%2;" : "=f"(r.x), "=f"(r.y) : "l"(a)); return r;
}

// ---------------- main ----------------
// dynamic smem layout (floats):
//   hbuf : 3 * CH * ROWP = 25344  @ 0       (ring of 64-row chunks)
//   wts  : 8 * ROWP      = 1056   @ 25344
//   encs : 512                    @ 26400   (signed 1/adj per row)
//   wsm  : 8*2*8 ull = 256 floats @ 26912   (per-warp w broadcast, dbl-buf)
//   zred : 64                     @ 27168
//   wred : 64                     @ 27232
//   invZ : 8                      @ 27296
//   was  : 16                     @ 27304
#define MAIN_SMEM_FLOATS 27320

__global__ __launch_bounds__(256, 2) void gat_main(const float* __restrict__ hin,
                                                   const float* __restrict__ adj,
                                                   const float* __restrict__ mask,
                                                   const float* __restrict__ W1,
                                                   const float* __restrict__ Wa) {
    extern __shared__ __align__(16) float sm[];
    float* hbuf = sm;
    float* wts  = sm + 25344;
    float* encs = sm + 26400;
    ull*   wsm  = (ull*)(sm + 26912);   // [warp][buf][8]
    float* zred = sm + 27168;
    float* wred = sm + 27232;
    float* invZ = sm + 27296;
    float* was  = sm + 27304;

    const int bt = blockIdx.x;
    const int b = bt >> 7;
    const int t = bt & 127;
    const int tid = threadIdx.x;
    const int warp = tid >> 5;
    const int lane = tid & 31;
    const int kc = lane;

    // ---- pure-DMA chunk loader ----
    auto issue_dma = [&](int c) {
        float* hb = hbuf + (c % 3) * (CH * ROWP);
        const float* base = hin + (((size_t)(b * Nv + c * CH)) * Tv + t) * Dv;
        #pragma unroll
        for (int i = 0; i < 8; i++) {
            int lin = i * 256 + tid;
            int r = lin >> 5;
            int j = lin & 31;
            const float* gp = base + (size_t)r * (Tv * Dv) + j * 4;
            unsigned sa = (unsigned)__cvta_generic_to_shared(&hb[r * ROWP + j * 4]);
            asm volatile("cp.async.cg.shared.global [%0], [%1], 16;" :: "r"(sa), "l"(gp));
        }
        asm volatile("cp.async.commit_group;");
    };

    issue_dma(0); issue_dma(1); issue_dma(2);

    // ---- one-time prologue: enc table + wtil (overlaps DMA) ----
    {
        float m0 = mask[(size_t)(b * Nv + tid) * Tv + t];
        float m1 = mask[(size_t)(b * Nv + tid + 256) * Tv + t];
        float a0 = adj[(size_t)(b * Tv + t) * Nv + tid];
        float a1 = adj[(size_t)(b * Tv + t) * Nv + tid + 256];
        a0 = (a0 == 0.f) ? 1e9f : a0;
        a1 = (a1 == 0.f) ? 1e9f : a1;
        encs[tid]       = (m0 > 0.5f ? 1.f : -1.f) * (1.0f / a0);
        encs[tid + 256] = (m1 > 0.5f ? 1.f : -1.f) * (1.0f / a1);
    }
    if (tid < 16) was[tid] = Wa[16 + tid];
    __syncthreads();
    for (int idx = tid; idx < 1024; idx += 256) {
        int hh = idx >> 7, k = idx & 127;
        const float* w1p = W1 + k * 128 + hh * 16;
        float a = 0.f;
        #pragma unroll
        for (int d = 0; d < 16; d++)
            a = fmaf(w1p[d], was[d], a);
        wts[hh * ROWP + k] = a;
    }
    __syncthreads();

    // wtil column-slice in registers
    ull wreg[16];
    #pragma unroll
    for (int h = 0; h < 8; h++) {
        ulonglong2 wv = *(const ulonglong2*)&wts[h * ROWP + kc * 4];
        wreg[2 * h] = wv.x;
        wreg[2 * h + 1] = wv.y;
    }

    ull acc[16];
    #pragma unroll
    for (int q = 0; q < 16; q++) acc[q] = 0ull;
    float zsum = 0.f, wsum = 0.f;

    const bool bb16 = (lane & 16) != 0;
    const bool bb8  = (lane & 8) != 0;
    const bool bb4  = (lane & 4) != 0;

    #pragma unroll 1
    for (int c = 0; c < NCHUNK; c++) {
        if (c < 6)       { asm volatile("cp.async.wait_group 2;"); }
        else if (c == 6) { asm volatile("cp.async.wait_group 1;"); }
        else             { asm volatile("cp.async.wait_group 0;"); }
        __syncthreads();
        const float* hb = hbuf + (c % 3) * (CH * ROWP);

        #pragma unroll
        for (int pr = 0; pr < 4; pr++) {
            const int r = warp * 8 + pr * 2;        // row within chunk
            ulonglong2 xa = *(const ulonglong2*)&hb[r * ROWP + kc * 4];
            ulonglong2 xb = *(const ulonglong2*)&hb[(r + 1) * ROWP + kc * 4];

            // score partials: sp[h] = (row r partial, row r+1 partial)
            ull sp[8];
            #pragma unroll
            for (int h = 0; h < 8; h++) {
                ull pa = f2fma(xa.y, wreg[2 * h + 1], f2mul(xa.x, wreg[2 * h]));
                ull pb = f2fma(xb.y, wreg[2 * h + 1], f2mul(xb.x, wreg[2 * h]));
                float2 qa = unpk(pa);
                float2 qb = unpk(pb);
                sp[h] = pack2(qa.x + qa.y, qb.x + qb.y);
            }

            // ownership-halving butterfly: quad q ends holding head q's scores
            ull v4[4];
            #pragma unroll
            for (int j = 0; j < 4; j++) {
                ull keep = bb16 ? sp[j + 4] : sp[j];
                ull send = bb16 ? sp[j] : sp[j + 4];
                v4[j] = f2add(keep, __shfl_xor_sync(0xffffffffu, send, 16));
            }
            ull v2[2];
            #pragma unroll
            for (int j = 0; j < 2; j++) {
                ull keep = bb8 ? v4[j + 2] : v4[j];
                ull send = bb8 ? v4[j] : v4[j + 2];
                v2[j] = f2add(keep, __shfl_xor_sync(0xffffffffu, send, 8));
            }
            ull v1;
            {
                ull keep = bb4 ? v2[1] : v2[0];
                ull send = bb4 ? v2[0] : v2[1];
                v1 = f2add(keep, __shfl_xor_sync(0xffffffffu, send, 4));
            }
            v1 = f2add(v1, __shfl_xor_sync(0xffffffffu, v1, 2));
            v1 = f2add(v1, __shfl_xor_sync(0xffffffffu, v1, 1));

            // e / w for owned head (all 4 lanes of quad hold identical v1)
            float en0 = encs[c * CH + r];
            float en1 = encs[c * CH + r + 1];
            float2 s = unpk(v1);
            float e0 = (en0 > 0.f) ? __expf(s.x) : 0.f;
            float e1 = (en1 > 0.f) ? __expf(s.y) : 0.f;
            float w0 = e0 * fabsf(en0);
            float w1 = e1 * fabsf(en1);
            zsum += e0 + e1;
            wsum += w0 + w1;

            // broadcast w via warp-private smem (lane 4h owns head h):
            // replaces 8 gather shuffles (16 shfl.32) with ~6 LSU wavefronts
            if ((lane & 3) == 0)
                wsm[warp * 16 + (pr & 1) * 8 + (lane >> 2)] = pack2(w0, w1);
            __syncwarp();
            const ull* wb = &wsm[warp * 16 + (pr & 1) * 8];
            ulonglong2 wp0 = *(const ulonglong2*)&wb[0];
            ulonglong2 wp1 = *(const ulonglong2*)&wb[2];
            ulonglong2 wp2 = *(const ulonglong2*)&wb[4];
            ulonglong2 wp3 = *(const ulonglong2*)&wb[6];

            ull whp[8] = { wp0.x, wp0.y, wp1.x, wp1.y, wp2.x, wp2.y, wp3.x, wp3.y };
            #pragma unroll
            for (int h = 0; h < 8; h++) {
                float2 wf = unpk(whp[h]);
                ull wr0 = packrep(wf.x);
                ull wr1 = packrep(wf.y);
                acc[2 * h]     = f2fma(wr0, xa.x, acc[2 * h]);
                acc[2 * h]     = f2fma(wr1, xb.x, acc[2 * h]);
                acc[2 * h + 1] = f2fma(wr0, xa.y, acc[2 * h + 1]);
                acc[2 * h + 1] = f2fma(wr1, xb.y, acc[2 * h + 1]);
            }
        }
        __syncthreads();                 // everyone done reading buf c%3
        if (c + 3 < NCHUNK) issue_dma(c + 3);
    }

    // ---- reduce Z, Sw per head (lane 4h of each warp holds head h) ----
    if ((lane & 3) == 0) {
        zred[warp * 8 + (lane >> 2)] = zsum;
        wred[warp * 8 + (lane >> 2)] = wsum;
    }
    __syncthreads();
    if (tid < 8) {
        float Z = 0.f, W = 0.f;
        #pragma unroll
        for (int i = 0; i < 8; i++) { Z += zred[i * 8 + tid]; W += wred[i * 8 + tid]; }
        float iZ = 1.0f / Z;
        invZ[tid] = iZ;
        S_scr[bt * 8 + tid] = W * iZ;
    }

    // ---- dump per-thread G partials into (reused) hbuf, tree-reduce, write ----
    {
        ull* red = (ull*)hbuf;   // 256 threads * 16 ull = 32 KB
        ulonglong2* my = (ulonglong2*)(red + (size_t)tid * 16);
        #pragma unroll
        for (int q = 0; q < 8; q++)
            my[q] = make_ulonglong2(acc[2 * q], acc[2 * q + 1]);
    }
    __syncthreads();
    {
        const ull* red = (const ull*)hbuf;
        #pragma unroll
        for (int o = 0; o < 2; o++) {
            int oi = tid * 2 + o;          // 0..511
            int hh  = oi >> 6;
            int kc2 = oi & 63;
            int kcc = kc2 >> 1, p = kc2 & 1;
            ull s = red[((size_t)kcc) * 16 + hh * 2 + p];
            #pragma unroll
            for (int g = 1; g < 8; g++)
                s = f2add(s, red[((size_t)(g * 32 + kcc)) * 16 + hh * 2 + p]);
            s = f2mul(s, packrep(invZ[hh]));
            ((ull*)G_scr)[(size_t)bt * 512 + hh * 64 + kc2] = s;
        }
    }
}

// ---------------- epilogue: 1024 lightweight blocks ----------------
__global__ __launch_bounds__(128) void gat_epi(const float* __restrict__ hin,
                                               const float* __restrict__ W1,
                                               const float* __restrict__ W2,
                                               const float* __restrict__ b1,
                                               const float* __restrict__ b2,
                                               float* __restrict__ out) {
    __shared__ __align__(16) float gs[8 * 132];
    __shared__ __align__(16) float h0s[128];
    __shared__ __align__(16) float aggs[128];
    __shared__ __align__(16) float ths[128];
    __shared__ float Ss[8];

    const int bt = blockIdx.x;
    const int b = bt >> 7;
    const int t = bt & 127;
    const int tid = threadIdx.x;

    #pragma unroll
    for (int i = 0; i < 8; i++) {
        int idx = i * 128 + tid;
        gs[(idx >> 7) * 132 + (idx & 127)] = G_scr[(size_t)bt * 1024 + idx];
    }
    h0s[tid] = hin[((size_t)(b * Nv) * Tv + t) * Dv + tid];
    if (tid < 8) Ss[tid] = S_scr[bt * 8 + tid];
    __syncthreads();

    {
        const int j = tid;
        const int hh = j >> 4;
        float bj = __ldg(&b1[j]);
        float agg = Ss[hh] * bj;
        float th = bj;
        const float* gp = &gs[hh * 132];
        #pragma unroll 8
        for (int m = 0; m < 128; m++) {
            float w = __ldg(&W1[m * 128 + j]);
            agg = fmaf(gp[m], w, agg);
            th  = fmaf(h0s[m], w, th);
        }
        aggs[j] = agg;
        ths[j] = th;
    }
    __syncthreads();

    {
        const int k = tid;
        float o = __ldg(&b2[k]);
        #pragma unroll 8
        for (int j = 0; j < 128; j++) {
            o = fmaf(aggs[j], __ldg(&W2[j * 128 + k]), o);
            o = fmaf(ths[j],  __ldg(&W2[(128 + j) * 128 + k]), o);
        }
        out[(size_t)bt * 128 + k] = o;
    }
}

// third kernel: keeps ncu's fixed capture slot on gat_main
__global__ void gat_nop() {}

// ---------------- launch ----------------
extern "C" void kernel_launch(void* const* d_in, const int* in_sizes, int n_in,
                              void* d_out, int out_size) {
    const float* h    = (const float*)d_in[0];
    const float* adj  = (const float*)d_in[1];
    const float* mask = (const float*)d_in[2];
    const float* W1   = (const float*)d_in[3];
    const float* b1   = (const float*)d_in[4];
    const float* Wa   = (const float*)d_in[5];
    // d_in[6] = ba (cancels in softmax; unused)
    const float* W2   = (const float*)d_in[7];
    const float* b2   = (const float*)d_in[8];
    float* out = (float*)d_out;

    cudaFuncSetAttribute(gat_main, cudaFuncAttributeMaxDynamicSharedMemorySize,
                         MAIN_SMEM_FLOATS * (int)sizeof(float));

    gat_main<<<Bv * Tv, 256, MAIN_SMEM_FLOATS * sizeof(float)>>>(h, adj, mask, W1, Wa);
    gat_epi<<<Bv * Tv, 128>>>(h, W1, W2, b1, b2, out);
    gat_nop<<<1, 32>>>();
}

// round 17
// speedup vs baseline: 1.0751x; 1.0444x over previous
#include <cuda_runtime.h>
#include <cuda_bf16.h>
#include <cstdint>

// GAT fused kernel, GB300 sm_103a.
// B=8, N=512, T=128, DIN=DOUT=128, H=8, HD=16.
//
// Factorization (exactly equivalent to reference):
//   softmax-effective score[b,t,h,n] = h[b,n,t,:] . wtil_h   (row-constant terms cancel)
//     wtil_h[k] = sum_d W1[k, h*16+d] * Wa[16+d]
//   e = mask * exp(score);  w = e * rv,  rv = 1/(adj==0 ? 1e9 : adj)
//   Z_h = sum_n e;  S_h = (sum_n w)/Z_h;  g_h = (sum_n w*h_n)/Z_h
//   agg[h*16+d] = g_h . W1[:, h*16+d] + S_h * b1[h*16+d]
//   th = h0 @ W1 + b1
//   out = agg @ W2[:128] + th @ W2[128:] + b2
//
// R17: per-warp private DMA pipelines, ZERO block barriers in the main loop.
// R11-R16 were phase-locked: per-chunk __syncthreads forced all warps of an
// SMSP into the serial shfl-butterfly chain simultaneously (issue stuck at
// 28%). Now warp w owns rows w*64..w*64+63 with a private 3-deep ring of
// 8-row buffers; cp.async wait_group is per-thread, and every lane reads only
// the bytes it DMA'd itself (lane kc writes float4 kc of each row), so
// wait_group + __syncwarp is sufficient. Warps free-run and desynchronize.

#define Bv 8
#define Nv 512
#define Tv 128
#define Dv 128
#define SUB 8       // rows per sub-chunk
#define NSUB 8      // sub-chunks per warp (64 rows)
#define RING 3
#define ROWP 132    // padded row pitch (floats)

typedef unsigned long long ull;

// ---------------- scratch ----------------
__device__ float G_scr[Bv * Tv * 8 * Dv];
__device__ float S_scr[Bv * Tv * 8];

// ---------------- f32x2 helpers ----------------
__device__ __forceinline__ ull f2fma(ull a, ull b, ull c) {
    ull d; asm("fma.rn.f32x2 %0,%1,%2,%3;" : "=l"(d) : "l"(a), "l"(b), "l"(c)); return d;
}
__device__ __forceinline__ ull f2add(ull a, ull b) {
    ull d; asm("add.rn.f32x2 %0,%1,%2;" : "=l"(d) : "l"(a), "l"(b)); return d;
}
__device__ __forceinline__ ull f2mul(ull a, ull b) {
    ull d; asm("mul.rn.f32x2 %0,%1,%2;" : "=l"(d) : "l"(a), "l"(b)); return d;
}
__device__ __forceinline__ ull packrep(float x) {
    ull d; asm("mov.b64 %0,{%1,%1};" : "=l"(d) : "f"(x)); return d;
}
__device__ __forceinline__ ull pack2(float x, float y) {
    ull d; asm("mov.b64 %0,{%1,%2};" : "=l"(d) : "f"(x), "f"(y)); return d;
}
__device__ __forceinline__ float2 unpk(ull a) {
    float2 r; asm("mov.b64 {%0,%1},%2;" : "=f"(r.x), "=f"(r.y) : "l"(a)); return r;
}

// ---------------- main ----------------
// dynamic smem layout (floats):
//   hbuf : 8 warps * RING * SUB * ROWP = 25344  @ 0   (per-warp rings)
//   wts  : 8 * ROWP = 1056                      @ 25344
//   encs : 512                                  @ 26400
//   wsm  : 8*2*8 ull = 256 floats               @ 26912
//   zred : 64                                   @ 27168
//   wred : 64                                   @ 27232
//   invZ : 8                                    @ 27296
//   was  : 16                                   @ 27304
#define MAIN_SMEM_FLOATS 27320

__global__ __launch_bounds__(256, 2) void gat_main(const float* __restrict__ hin,
                                                   const float* __restrict__ adj,
                                                   const float* __restrict__ mask,
                                                   const float* __restrict__ W1,
                                                   const float* __restrict__ Wa) {
    extern __shared__ __align__(16) float sm[];
    float* hbuf = sm;
    float* wts  = sm + 25344;
    float* encs = sm + 26400;
    ull*   wsm  = (ull*)(sm + 26912);   // [warp][buf][8]
    float* zred = sm + 27168;
    float* wred = sm + 27232;
    float* invZ = sm + 27296;
    float* was  = sm + 27304;

    const int bt = blockIdx.x;
    const int b = bt >> 7;
    const int t = bt & 127;
    const int tid = threadIdx.x;
    const int warp = tid >> 5;
    const int lane = tid & 31;
    const int kc = lane;

    float* mybuf = hbuf + warp * (RING * SUB * ROWP);

    // ---- per-warp DMA: sub-chunk s = rows warp*64 + s*8 .. +7 ----
    // lane j loads float4 j of every row (so each lane later reads ONLY its
    // own cp.async bytes -> wait_group + syncwarp is sufficient).
    auto issue_sub = [&](int s) {
        float* hb = mybuf + (s % RING) * (SUB * ROWP);
        const float* base = hin + (((size_t)(b * Nv + warp * 64 + s * SUB)) * Tv + t) * Dv;
        #pragma unroll
        for (int i = 0; i < SUB; i++) {
            const float* gp = base + (size_t)i * (Tv * Dv) + lane * 4;
            unsigned sa = (unsigned)__cvta_generic_to_shared(&hb[i * ROWP + lane * 4]);
            asm volatile("cp.async.cg.shared.global [%0], [%1], 16;" :: "r"(sa), "l"(gp));
        }
        asm volatile("cp.async.commit_group;");
    };

    issue_sub(0); issue_sub(1); issue_sub(2);

    // ---- one-time prologue: enc table + wtil (overlaps DMA) ----
    {
        float m0 = mask[(size_t)(b * Nv + tid) * Tv + t];
        float m1 = mask[(size_t)(b * Nv + tid + 256) * Tv + t];
        float a0 = adj[(size_t)(b * Tv + t) * Nv + tid];
        float a1 = adj[(size_t)(b * Tv + t) * Nv + tid + 256];
        a0 = (a0 == 0.f) ? 1e9f : a0;
        a1 = (a1 == 0.f) ? 1e9f : a1;
        encs[tid]       = (m0 > 0.5f ? 1.f : -1.f) * (1.0f / a0);
        encs[tid + 256] = (m1 > 0.5f ? 1.f : -1.f) * (1.0f / a1);
    }
    if (tid < 16) was[tid] = Wa[16 + tid];
    __syncthreads();
    for (int idx = tid; idx < 1024; idx += 256) {
        int hh = idx >> 7, k = idx & 127;
        const float* w1p = W1 + k * 128 + hh * 16;
        float a = 0.f;
        #pragma unroll
        for (int d = 0; d < 16; d++)
            a = fmaf(w1p[d], was[d], a);
        wts[hh * ROWP + k] = a;
    }
    __syncthreads();   // encs + wts visible to all; the ONLY pre-loop barrier

    // wtil column-slice in registers
    ull wreg[16];
    #pragma unroll
    for (int h = 0; h < 8; h++) {
        ulonglong2 wv = *(const ulonglong2*)&wts[h * ROWP + kc * 4];
        wreg[2 * h] = wv.x;
        wreg[2 * h + 1] = wv.y;
    }

    ull acc[16];
    #pragma unroll
    for (int q = 0; q < 16; q++) acc[q] = 0ull;
    float zsum = 0.f, wsum = 0.f;

    const bool bb16 = (lane & 16) != 0;
    const bool bb8  = (lane & 8) != 0;
    const bool bb4  = (lane & 4) != 0;

    // ---- free-running per-warp main loop (no block barriers) ----
    #pragma unroll 1
    for (int s = 0; s < NSUB; s++) {
        const int rem = NSUB - 1 - s;
        if (rem >= 2)      { asm volatile("cp.async.wait_group 2;"); }
        else if (rem == 1) { asm volatile("cp.async.wait_group 1;"); }
        else               { asm volatile("cp.async.wait_group 0;"); }
        __syncwarp();
        const float* hb = mybuf + (s % RING) * (SUB * ROWP);
        const int ebase = warp * 64 + s * SUB;

        #pragma unroll
        for (int pr = 0; pr < 4; pr++) {
            const int r = pr * 2;
            ulonglong2 xa = *(const ulonglong2*)&hb[r * ROWP + kc * 4];
            ulonglong2 xb = *(const ulonglong2*)&hb[(r + 1) * ROWP + kc * 4];

            // score partials: sp[h] = (row r partial, row r+1 partial)
            ull sp[8];
            #pragma unroll
            for (int h = 0; h < 8; h++) {
                ull pa = f2fma(xa.y, wreg[2 * h + 1], f2mul(xa.x, wreg[2 * h]));
                ull pb = f2fma(xb.y, wreg[2 * h + 1], f2mul(xb.x, wreg[2 * h]));
                float2 qa = unpk(pa);
                float2 qb = unpk(pb);
                sp[h] = pack2(qa.x + qa.y, qb.x + qb.y);
            }

            // ownership-halving butterfly: quad q ends holding head q's scores
            ull v4[4];
            #pragma unroll
            for (int j = 0; j < 4; j++) {
                ull keep = bb16 ? sp[j + 4] : sp[j];
                ull send = bb16 ? sp[j] : sp[j + 4];
                v4[j] = f2add(keep, __shfl_xor_sync(0xffffffffu, send, 16));
            }
            ull v2[2];
            #pragma unroll
            for (int j = 0; j < 2; j++) {
                ull keep = bb8 ? v4[j + 2] : v4[j];
                ull send = bb8 ? v4[j] : v4[j + 2];
                v2[j] = f2add(keep, __shfl_xor_sync(0xffffffffu, send, 8));
            }
            ull v1;
            {
                ull keep = bb4 ? v2[1] : v2[0];
                ull send = bb4 ? v2[0] : v2[1];
                v1 = f2add(keep, __shfl_xor_sync(0xffffffffu, send, 4));
            }
            v1 = f2add(v1, __shfl_xor_sync(0xffffffffu, v1, 2));
            v1 = f2add(v1, __shfl_xor_sync(0xffffffffu, v1, 1));

            // e / w for owned head (all 4 lanes of quad hold identical v1)
            float en0 = encs[ebase + r];
            float en1 = encs[ebase + r + 1];
            float2 sc = unpk(v1);
            float e0 = (en0 > 0.f) ? __expf(sc.x) : 0.f;
            float e1 = (en1 > 0.f) ? __expf(sc.y) : 0.f;
            float w0 = e0 * fabsf(en0);
            float w1 = e1 * fabsf(en1);
            zsum += e0 + e1;
            wsum += w0 + w1;

            // broadcast w via warp-private smem (lane 4h owns head h)
            if ((lane & 3) == 0)
                wsm[warp * 16 + (pr & 1) * 8 + (lane >> 2)] = pack2(w0, w1);
            __syncwarp();
            const ull* wb = &wsm[warp * 16 + (pr & 1) * 8];
            ulonglong2 wp0 = *(const ulonglong2*)&wb[0];
            ulonglong2 wp1 = *(const ulonglong2*)&wb[2];
            ulonglong2 wp2 = *(const ulonglong2*)&wb[4];
            ulonglong2 wp3 = *(const ulonglong2*)&wb[6];

            ull whp[8] = { wp0.x, wp0.y, wp1.x, wp1.y, wp2.x, wp2.y, wp3.x, wp3.y };
            #pragma unroll
            for (int h = 0; h < 8; h++) {
                float2 wf = unpk(whp[h]);
                ull wr0 = packrep(wf.x);
                ull wr1 = packrep(wf.y);
                acc[2 * h]     = f2fma(wr0, xa.x, acc[2 * h]);
                acc[2 * h]     = f2fma(wr1, xb.x, acc[2 * h]);
                acc[2 * h + 1] = f2fma(wr0, xa.y, acc[2 * h + 1]);
                acc[2 * h + 1] = f2fma(wr1, xb.y, acc[2 * h + 1]);
            }
        }
        if (s + RING < NSUB) issue_sub(s + RING);
    }

    // ---- reduce Z, Sw per head (lane 4h of each warp holds head h) ----
    if ((lane & 3) == 0) {
        zred[warp * 8 + (lane >> 2)] = zsum;
        wred[warp * 8 + (lane >> 2)] = wsum;
    }
    __syncthreads();
    if (tid < 8) {
        float Z = 0.f, W = 0.f;
        #pragma unroll
        for (int i = 0; i < 8; i++) { Z += zred[i * 8 + tid]; W += wred[i * 8 + tid]; }
        float iZ = 1.0f / Z;
        invZ[tid] = iZ;
        S_scr[bt * 8 + tid] = W * iZ;
    }

    // ---- dump per-thread G partials into (reused) hbuf, tree-reduce, write ----
    {
        ull* red = (ull*)hbuf;   // 256 threads * 16 ull = 32 KB
        ulonglong2* my = (ulonglong2*)(red + (size_t)tid * 16);
        #pragma unroll
        for (int q = 0; q < 8; q++)
            my[q] = make_ulonglong2(acc[2 * q], acc[2 * q + 1]);
    }
    __syncthreads();
    {
        const ull* red = (const ull*)hbuf;
        #pragma unroll
        for (int o = 0; o < 2; o++) {
            int oi = tid * 2 + o;          // 0..511
            int hh  = oi >> 6;
            int kc2 = oi & 63;
            int kcc = kc2 >> 1, p = kc2 & 1;
            ull s = red[((size_t)kcc) * 16 + hh * 2 + p];
            #pragma unroll
            for (int g = 1; g < 8; g++)
                s = f2add(s, red[((size_t)(g * 32 + kcc)) * 16 + hh * 2 + p]);
            s = f2mul(s, packrep(invZ[hh]));
            ((ull*)G_scr)[(size_t)bt * 512 + hh * 64 + kc2] = s;
        }
    }
}

// ---------------- epilogue: 1024 lightweight blocks ----------------
__global__ __launch_bounds__(128) void gat_epi(const float* __restrict__ hin,
                                               const float* __restrict__ W1,
                                               const float* __restrict__ W2,
                                               const float* __restrict__ b1,
                                               const float* __restrict__ b2,
                                               float* __restrict__ out) {
    __shared__ __align__(16) float gs[8 * 132];
    __shared__ __align__(16) float h0s[128];
    __shared__ __align__(16) float aggs[128];
    __shared__ __align__(16) float ths[128];
    __shared__ float Ss[8];

    const int bt = blockIdx.x;
    const int b = bt >> 7;
    const int t = bt & 127;
    const int tid = threadIdx.x;

    #pragma unroll
    for (int i = 0; i < 8; i++) {
        int idx = i * 128 + tid;
        gs[(idx >> 7) * 132 + (idx & 127)] = G_scr[(size_t)bt * 1024 + idx];
    }
    h0s[tid] = hin[((size_t)(b * Nv) * Tv + t) * Dv + tid];
    if (tid < 8) Ss[tid] = S_scr[bt * 8 + tid];
    __syncthreads();

    {
        const int j = tid;
        const int hh = j >> 4;
        float bj = __ldg(&b1[j]);
        float agg = Ss[hh] * bj;
        float th = bj;
        const float* gp = &gs[hh * 132];
        #pragma unroll 8
        for (int m = 0; m < 128; m++) {
            float w = __ldg(&W1[m * 128 + j]);
            agg = fmaf(gp[m], w, agg);
            th  = fmaf(h0s[m], w, th);
        }
        aggs[j] = agg;
        ths[j] = th;
    }
    __syncthreads();

    {
        const int k = tid;
        float o = __ldg(&b2[k]);
        #pragma unroll 8
        for (int j = 0; j < 128; j++) {
            o = fmaf(aggs[j], __ldg(&W2[j * 128 + k]), o);
            o = fmaf(ths[j],  __ldg(&W2[(128 + j) * 128 + k]), o);
        }
        out[(size_t)bt * 128 + k] = o;
    }
}

// third kernel: keeps ncu's fixed capture slot on gat_main
__global__ void gat_nop() {}

// ---------------- launch ----------------
extern "C" void kernel_launch(void* const* d_in, const int* in_sizes, int n_in,
                              void* d_out, int out_size) {
    const float* h    = (const float*)d_in[0];
    const float* adj  = (const float*)d_in[1];
    const float* mask = (const float*)d_in[2];
    const float* W1   = (const float*)d_in[3];
    const float* b1   = (const float*)d_in[4];
    const float* Wa   = (const float*)d_in[5];
    // d_in[6] = ba (cancels in softmax; unused)
    const float* W2   = (const float*)d_in[7];
    const float* b2   = (const float*)d_in[8];
    float* out = (float*)d_out;

    cudaFuncSetAttribute(gat_main, cudaFuncAttributeMaxDynamicSharedMemorySize,
                         MAIN_SMEM_FLOATS * (int)sizeof(float));

    gat_main<<<Bv * Tv, 256, MAIN_SMEM_FLOATS * sizeof(float)>>>(h, adj, mask, W1, Wa);
    gat_epi<<<Bv * Tv, 128>>>(h, W1, W2, b1, b2, out);
    gat_nop<<<1, 32>>>();
}